// round 1
// baseline (speedup 1.0000x reference)
#include <cuda_runtime.h>
#include <math.h>

// ---------------- scratch (no allocs allowed) ----------------
__device__ float g_xn[8192 * 1024];   // layernormed x
__device__ float g_qkv[8192 * 3072];  // qkv projection (q,k normed in place)
__device__ float g_ao[8192 * 1024];   // attention out, [b*n][h*64+d]

#define DIMM 1024
#define HEADS 16
#define DH 64

// ---------------- LayerNorm: one block per row of 1024 ----------------
__global__ __launch_bounds__(256) void ln_kernel(const float* __restrict__ x,
                                                 const float* __restrict__ g,
                                                 float* __restrict__ o) {
    int row = blockIdx.x;
    int tid = threadIdx.x;
    const float* xr = x + (size_t)row * DIMM;
    float4 v = *(const float4*)(xr + tid * 4);
    float s  = v.x + v.y + v.z + v.w;
    float ss = v.x * v.x + v.y * v.y + v.z * v.z + v.w * v.w;
#pragma unroll
    for (int off = 16; off; off >>= 1) {
        s  += __shfl_xor_sync(0xffffffffu, s, off);
        ss += __shfl_xor_sync(0xffffffffu, ss, off);
    }
    __shared__ float rs[8], rss[8];
    __shared__ float mu_s, rstd_s;
    int w = tid >> 5, lane = tid & 31;
    if (!lane) { rs[w] = s; rss[w] = ss; }
    __syncthreads();
    if (tid == 0) {
        float S = 0.f, SS = 0.f;
#pragma unroll
        for (int i = 0; i < 8; i++) { S += rs[i]; SS += rss[i]; }
        float mu  = S * (1.0f / DIMM);
        float var = SS * (1.0f / DIMM) - mu * mu;
        mu_s = mu;
        rstd_s = rsqrtf(var + 1e-5f);
    }
    __syncthreads();
    float mu = mu_s, r = rstd_s;
    float4 gv = *(const float4*)(g + tid * 4);
    float4 ov;
    ov.x = (v.x - mu) * r * gv.x;
    ov.y = (v.y - mu) * r * gv.y;
    ov.z = (v.z - mu) * r * gv.z;
    ov.w = (v.w - mu) * r * gv.w;
    *(float4*)(o + (size_t)row * DIMM + tid * 4) = ov;
}

// ---------------- SGEMM: C[M,N] = A[M,K] @ B[K,N], all row-major ----------------
// BM=BN=128, BK=8, 256 threads, 8x8 microtile. Dims assumed multiples of tile.
__global__ __launch_bounds__(256) void sgemm128(const float* __restrict__ A,
                                                const float* __restrict__ B,
                                                float* __restrict__ C,
                                                int M, int N, int K) {
    __shared__ float As[8 * 128];  // transposed: As[k][m]
    __shared__ float Bs[8 * 128];  // Bs[k][n]
    int tid = threadIdx.x;
    int row0 = blockIdx.y * 128;
    int col0 = blockIdx.x * 128;
    int ty = tid >> 4;  // 0..15
    int tx = tid & 15;  // 0..15

    float acc[8][8];
#pragma unroll
    for (int i = 0; i < 8; i++)
#pragma unroll
        for (int j = 0; j < 8; j++) acc[i][j] = 0.f;

    int ar  = tid >> 1;          // 0..127
    int ac4 = (tid & 1) * 4;     // 0 or 4
    int br  = tid >> 5;          // 0..7
    int bc4 = (tid & 31) * 4;    // 0..124

    const float* Aptr = A + (size_t)(row0 + ar) * K + ac4;
    const float* Bptr = B + (size_t)br * N + col0 + bc4;

    for (int k0 = 0; k0 < K; k0 += 8) {
        float4 av = *(const float4*)(Aptr + k0);
        float4 bv = *(const float4*)(Bptr + (size_t)k0 * N);
        As[(ac4 + 0) * 128 + ar] = av.x;
        As[(ac4 + 1) * 128 + ar] = av.y;
        As[(ac4 + 2) * 128 + ar] = av.z;
        As[(ac4 + 3) * 128 + ar] = av.w;
        *(float4*)(&Bs[br * 128 + bc4]) = bv;
        __syncthreads();
#pragma unroll
        for (int k = 0; k < 8; k++) {
            float ra[8], rb[8];
            *(float4*)&ra[0] = *(const float4*)&As[k * 128 + ty * 8];
            *(float4*)&ra[4] = *(const float4*)&As[k * 128 + ty * 8 + 4];
            *(float4*)&rb[0] = *(const float4*)&Bs[k * 128 + tx * 8];
            *(float4*)&rb[4] = *(const float4*)&Bs[k * 128 + tx * 8 + 4];
#pragma unroll
            for (int i = 0; i < 8; i++)
#pragma unroll
                for (int j = 0; j < 8; j++) acc[i][j] += ra[i] * rb[j];
        }
        __syncthreads();
    }

#pragma unroll
    for (int i = 0; i < 8; i++) {
        float* cr = C + (size_t)(row0 + ty * 8 + i) * N + col0 + tx * 8;
        float4 o0 = make_float4(acc[i][0], acc[i][1], acc[i][2], acc[i][3]);
        float4 o1 = make_float4(acc[i][4], acc[i][5], acc[i][6], acc[i][7]);
        *(float4*)cr = o0;
        *(float4*)(cr + 4) = o1;
    }
}

// ---------------- per-head RMS norm of q and k (in place), warp per 64-vec ----------------
__global__ __launch_bounds__(256) void rms_kernel(float* __restrict__ qkv,
                                                  const float* __restrict__ qg,
                                                  const float* __restrict__ kg) {
    int w = (blockIdx.x * 256 + threadIdx.x) >> 5;  // 0 .. 262143
    int lane = threadIdx.x & 31;
    int qk  = w >> 17;          // 0=q, 1=k
    int rem = w & 131071;
    int row = rem >> 4;         // b*1024+n
    int h   = rem & 15;
    float* p = qkv + (size_t)row * 3072 + qk * 1024 + h * DH + lane * 2;
    float2 v = *(float2*)p;
    float ss = v.x * v.x + v.y * v.y;
#pragma unroll
    for (int off = 16; off; off >>= 1) ss += __shfl_xor_sync(0xffffffffu, ss, off);
    float n = sqrtf(ss);
    float sc = 8.0f / fmaxf(n, 1e-12f);  // sqrt(64)=8
    const float* g = (qk ? kg : qg) + h * DH + lane * 2;
    v.x *= sc * g[0];
    v.y *= sc * g[1];
    *(float2*)p = v;
}

// ---------------- fused flash attention ----------------
// grid: (16 i-tiles, 128 bh). block 256 threads.
// thread (ti = tid>>2 : local q row, tx = tid&3 : column group, j = jj*4+tx interleaved)
#define KSTR 68
#define ATTN_SMEM (3 * 64 * KSTR * 4)

__global__ __launch_bounds__(256, 2) void attn_kernel(const float* __restrict__ qkv,
                                                      float* __restrict__ out) {
    extern __shared__ float sm[];
    float* Ks = sm;                // [64][KSTR]
    float* Vs = sm + 64 * KSTR;    // [64][KSTR]
    float* Ps = sm + 2 * 64 * KSTR;

    int bh = blockIdx.y;
    int b = bh >> 4, h = bh & 15;
    int i0 = blockIdx.x * 64;
    int tid = threadIdx.x;
    int ti = tid >> 2;  // 0..63
    int tx = tid & 3;   // 0..3

    const float* base  = qkv + (size_t)b * 1024 * 3072 + h * DH;
    const float* qbase = base;
    const float* kbase = base + 1024;
    const float* vbase = base + 2048;

    // Q row in registers (already RMS-normed)
    float4 q[16];
    {
        const float4* qp = (const float4*)(qbase + (size_t)(i0 + ti) * 3072);
#pragma unroll
        for (int d4 = 0; d4 < 16; d4++) q[d4] = qp[d4];
    }

    float4 O[4];
#pragma unroll
    for (int z = 0; z < 4; z++) O[z] = make_float4(0.f, 0.f, 0.f, 0.f);
    float m = -1e30f, l = 0.f;

    for (int jt = 0; jt < 16; jt++) {
        __syncthreads();
        int j0 = jt * 64;
        // load K,V tiles
        for (int t = tid; t < 1024; t += 256) {
            int r = t >> 4, c4 = (t & 15) * 4;
            *(float4*)(Ks + r * KSTR + c4) = *(const float4*)(kbase + (size_t)(j0 + r) * 3072 + c4);
            *(float4*)(Vs + r * KSTR + c4) = *(const float4*)(vbase + (size_t)(j0 + r) * 3072 + c4);
        }
        __syncthreads();

        // S = q . k  (16 j's per thread, interleaved j = jj*4+tx)
        float s[16];
#pragma unroll
        for (int jj = 0; jj < 16; jj++) {
            int j = jj * 4 + tx;
            const float4* kp = (const float4*)(Ks + j * KSTR);
            float4 a = make_float4(0.f, 0.f, 0.f, 0.f);
#pragma unroll
            for (int d4 = 0; d4 < 16; d4++) {
                float4 kv = kp[d4];
                a.x += q[d4].x * kv.x;
                a.y += q[d4].y * kv.y;
                a.z += q[d4].z * kv.z;
                a.w += q[d4].w * kv.w;
            }
            s[jj] = (a.x + a.y) + (a.z + a.w);
        }

        // online softmax over this tile
        float mt = s[0];
#pragma unroll
        for (int jj = 1; jj < 16; jj++) mt = fmaxf(mt, s[jj]);
        mt = fmaxf(mt, __shfl_xor_sync(0xffffffffu, mt, 1));
        mt = fmaxf(mt, __shfl_xor_sync(0xffffffffu, mt, 2));
        float mnew = fmaxf(m, mt);
        float scale = __expf(m - mnew);
        float ls = 0.f;
#pragma unroll
        for (int jj = 0; jj < 16; jj++) {
            s[jj] = __expf(s[jj] - mnew);
            ls += s[jj];
        }
        ls += __shfl_xor_sync(0xffffffffu, ls, 1);
        ls += __shfl_xor_sync(0xffffffffu, ls, 2);
        l = l * scale + ls;
        m = mnew;

        // store P tile
#pragma unroll
        for (int jj = 0; jj < 16; jj++) Ps[ti * KSTR + jj * 4 + tx] = s[jj];

        // rescale O
#pragma unroll
        for (int z = 0; z < 4; z++) {
            O[z].x *= scale; O[z].y *= scale; O[z].z *= scale; O[z].w *= scale;
        }
        __syncthreads();

        // O += P @ V   (thread owns d = tx*16 .. tx*16+15)
#pragma unroll 4
        for (int j = 0; j < 64; j++) {
            float pv = Ps[ti * KSTR + j];
            const float4* vp = (const float4*)(Vs + j * KSTR + tx * 16);
#pragma unroll
            for (int d4 = 0; d4 < 4; d4++) {
                float4 vv = vp[d4];
                O[d4].x += pv * vv.x;
                O[d4].y += pv * vv.y;
                O[d4].z += pv * vv.z;
                O[d4].w += pv * vv.w;
            }
        }
    }

    float inv = 1.0f / l;
    float* op = out + (size_t)(b * 1024 + i0 + ti) * 1024 + h * DH + tx * 16;
#pragma unroll
    for (int d4 = 0; d4 < 4; d4++) {
        float4 o = O[d4];
        o.x *= inv; o.y *= inv; o.z *= inv; o.w *= inv;
        *(float4*)(op + d4 * 4) = o;
    }
}

// ---------------- launch ----------------
extern "C" void kernel_launch(void* const* d_in, const int* in_sizes, int n_in,
                              void* d_out, int out_size) {
    const float* x     = (const float*)d_in[0];
    const float* ln_g  = (const float*)d_in[1];
    const float* qg    = (const float*)d_in[2];
    const float* kg    = (const float*)d_in[3];
    const float* wqkv  = (const float*)d_in[4];
    const float* wout  = (const float*)d_in[5];
    float* out = (float*)d_out;

    float *xn, *qkv, *ao;
    cudaGetSymbolAddress((void**)&xn, g_xn);
    cudaGetSymbolAddress((void**)&qkv, g_qkv);
    cudaGetSymbolAddress((void**)&ao, g_ao);

    cudaFuncSetAttribute((const void*)attn_kernel,
                         cudaFuncAttributeMaxDynamicSharedMemorySize, ATTN_SMEM);

    ln_kernel<<<8192, 256>>>(x, ln_g, xn);
    sgemm128<<<dim3(3072 / 128, 8192 / 128), 256>>>(xn, wqkv, qkv, 8192, 3072, 1024);
    rms_kernel<<<32768, 256>>>(qkv, qg, kg);
    attn_kernel<<<dim3(16, 128), 256, ATTN_SMEM>>>(qkv, ao);
    sgemm128<<<dim3(1024 / 128, 8192 / 128), 256>>>(ao, wout, out, 8192, 1024, 1024);
}

// round 7
// speedup vs baseline: 1.3132x; 1.3132x over previous
#include <cuda_runtime.h>
#include <cuda_bf16.h>
#include <math.h>
#include <stdint.h>

// ---------------- scratch (no allocs allowed) ----------------
__device__ float g_xn[8192 * 1024];    // layernormed x
__device__ float g_qkv[8192 * 3072];   // qkv projection (q,k normed in place)
__device__ float g_ao[8192 * 1024];    // attention out
__device__ float g_wt[3072 * 1024];    // w_qkv transposed  [N][K]
__device__ float g_wt2[1024 * 1024];   // w_out transposed  [N][K]

#define DIMM 1024
#define HEADS 16
#define DH 64

// ================= helpers =================
static __device__ __forceinline__ uint32_t s2u(const void* p) {
    uint32_t a;
    asm("{ .reg .u64 t; cvta.to.shared.u64 t, %1; cvt.u32.u64 %0, t; }" : "=r"(a) : "l"(p));
    return a;
}
static __device__ __forceinline__ void ldm4(uint32_t* r, uint32_t addr) {
    asm volatile("ldmatrix.sync.aligned.m8n8.x4.shared.b16 {%0,%1,%2,%3}, [%4];"
                 : "=r"(r[0]), "=r"(r[1]), "=r"(r[2]), "=r"(r[3]) : "r"(addr));
}
static __device__ __forceinline__ void ldm2(uint32_t* r, uint32_t addr) {
    asm volatile("ldmatrix.sync.aligned.m8n8.x2.shared.b16 {%0,%1}, [%2];"
                 : "=r"(r[0]), "=r"(r[1]) : "r"(addr));
}
static __device__ __forceinline__ void mma16816(float* c, const uint32_t* a, const uint32_t* b) {
    asm volatile(
        "mma.sync.aligned.m16n8k16.row.col.f32.bf16.bf16.f32 "
        "{%0,%1,%2,%3}, {%4,%5,%6,%7}, {%8,%9}, {%0,%1,%2,%3};"
        : "+f"(c[0]), "+f"(c[1]), "+f"(c[2]), "+f"(c[3])
        : "r"(a[0]), "r"(a[1]), "r"(a[2]), "r"(a[3]), "r"(b[0]), "r"(b[1]));
}
static __device__ __forceinline__ uint32_t packbf(__nv_bfloat16 a, __nv_bfloat16 b) {
    return (uint32_t)__bfloat16_as_ushort(a) | ((uint32_t)__bfloat16_as_ushort(b) << 16);
}

// ---------------- LayerNorm: one block per row of 1024 ----------------
__global__ __launch_bounds__(256) void ln_kernel(const float* __restrict__ x,
                                                 const float* __restrict__ g,
                                                 float* __restrict__ o) {
    int row = blockIdx.x;
    int tid = threadIdx.x;
    const float* xr = x + (size_t)row * DIMM;
    float4 v = *(const float4*)(xr + tid * 4);
    float s  = v.x + v.y + v.z + v.w;
    float ss = v.x * v.x + v.y * v.y + v.z * v.z + v.w * v.w;
#pragma unroll
    for (int off = 16; off; off >>= 1) {
        s  += __shfl_xor_sync(0xffffffffu, s, off);
        ss += __shfl_xor_sync(0xffffffffu, ss, off);
    }
    __shared__ float rs[8], rss[8];
    __shared__ float mu_s, rstd_s;
    int w = tid >> 5, lane = tid & 31;
    if (!lane) { rs[w] = s; rss[w] = ss; }
    __syncthreads();
    if (tid == 0) {
        float S = 0.f, SS = 0.f;
#pragma unroll
        for (int i = 0; i < 8; i++) { S += rs[i]; SS += rss[i]; }
        float mu  = S * (1.0f / DIMM);
        float var = SS * (1.0f / DIMM) - mu * mu;
        mu_s = mu;
        rstd_s = rsqrtf(var + 1e-5f);
    }
    __syncthreads();
    float mu = mu_s, r = rstd_s;
    float4 gv = *(const float4*)(g + tid * 4);
    float4 ov;
    ov.x = (v.x - mu) * r * gv.x;
    ov.y = (v.y - mu) * r * gv.y;
    ov.z = (v.z - mu) * r * gv.z;
    ov.w = (v.w - mu) * r * gv.w;
    *(float4*)(o + (size_t)row * DIMM + tid * 4) = ov;
}

// ---------------- transpose: out[C][R] = in[R][C]^T ----------------
__global__ __launch_bounds__(256) void transpose_kernel(const float* __restrict__ in,
                                                        float* __restrict__ out,
                                                        int R, int C) {
    __shared__ float t[32][33];
    int bx = blockIdx.x * 32;
    int by = blockIdx.y * 32;
    int tx = threadIdx.x & 31, ty = threadIdx.x >> 5;
#pragma unroll
    for (int j = 0; j < 32; j += 8)
        t[ty + j][tx] = in[(size_t)(by + ty + j) * C + bx + tx];
    __syncthreads();
#pragma unroll
    for (int j = 0; j < 32; j += 8)
        out[(size_t)(bx + ty + j) * R + by + tx] = t[tx][ty + j];
}

// ---------------- bf16x2-split tensor-core GEMM ----------------
// C[M,N] = A[M,K] @ Bt[N,K]^T.  128x128 CTA tile, BK=32, 8 warps (2x4),
// mma.sync m16n8k16 bf16, split A=Ah+Al, B=Bh+Bl, 3 products (hh, hl, lh).
// smem rows padded to 80B so ldmatrix lane addresses hit 8 distinct 16B phases.
#define APITCH 80

__global__ __launch_bounds__(256, 2) void gemm_bf16(const float* __restrict__ A,
                                                    const float* __restrict__ Bt,
                                                    float* __restrict__ C,
                                                    int M, int N, int K) {
    __shared__ __align__(1024) unsigned char sm[4 * 128 * APITCH];  // 40960 B
    uint32_t sb = s2u(sm);
    const uint32_t AH = 0, AL = 128 * APITCH, BH = 2 * 128 * APITCH, BL = 3 * 128 * APITCH;

    int tid = threadIdx.x;
    int lane = tid & 31;
    int w = tid >> 5;
    int wm = w & 1;        // 2 warps along M
    int wn = w >> 1;       // 4 warps along N
    int row0 = blockIdx.y * 128, col0 = blockIdx.x * 128;

    float acc[4][4][4];
#pragma unroll
    for (int i = 0; i < 4; i++)
#pragma unroll
        for (int j = 0; j < 4; j++)
#pragma unroll
            for (int q = 0; q < 4; q++) acc[i][j][q] = 0.f;

    // ldmatrix per-lane address offsets
    uint32_t aoff = (uint32_t)(lane & 15) * APITCH + (uint32_t)(lane >> 4) * 16;
    uint32_t l16 = lane & 15;
    uint32_t boff = (l16 & 7) * APITCH + ((l16 >> 3) & 1) * 16;

    const int nchunk = K >> 5;
    for (int c = 0; c < nchunk; c++) {
        __syncthreads();
        // ---- fill smem: load fp32, split into bf16 hi/lo ----
#pragma unroll
        for (int it = 0; it < 4; it++) {
            int idx = tid + it * 256;       // 0..1023
            int r = idx >> 3;               // 0..127
            int f4 = idx & 7;               // float4 within 32-float row
            uint32_t so = (uint32_t)r * APITCH + (uint32_t)f4 * 8;

            float4 va = *(const float4*)(A + (size_t)(row0 + r) * K + c * 32 + f4 * 4);
            __nv_bfloat16 hx = __float2bfloat16_rn(va.x);
            __nv_bfloat16 hy = __float2bfloat16_rn(va.y);
            __nv_bfloat16 hz = __float2bfloat16_rn(va.z);
            __nv_bfloat16 hw = __float2bfloat16_rn(va.w);
            uint2 hi, lo;
            hi.x = packbf(hx, hy);
            hi.y = packbf(hz, hw);
            lo.x = packbf(__float2bfloat16_rn(va.x - __bfloat162float(hx)),
                          __float2bfloat16_rn(va.y - __bfloat162float(hy)));
            lo.y = packbf(__float2bfloat16_rn(va.z - __bfloat162float(hz)),
                          __float2bfloat16_rn(va.w - __bfloat162float(hw)));
            *(uint2*)(sm + AH + so) = hi;
            *(uint2*)(sm + AL + so) = lo;

            float4 vb = *(const float4*)(Bt + (size_t)(col0 + r) * K + c * 32 + f4 * 4);
            hx = __float2bfloat16_rn(vb.x);
            hy = __float2bfloat16_rn(vb.y);
            hz = __float2bfloat16_rn(vb.z);
            hw = __float2bfloat16_rn(vb.w);
            hi.x = packbf(hx, hy);
            hi.y = packbf(hz, hw);
            lo.x = packbf(__float2bfloat16_rn(vb.x - __bfloat162float(hx)),
                          __float2bfloat16_rn(vb.y - __bfloat162float(hy)));
            lo.y = packbf(__float2bfloat16_rn(vb.z - __bfloat162float(hz)),
                          __float2bfloat16_rn(vb.w - __bfloat162float(hw)));
            *(uint2*)(sm + BH + so) = hi;
            *(uint2*)(sm + BL + so) = lo;
        }
        __syncthreads();

        // ---- compute ----
#pragma unroll
        for (int ks = 0; ks < 2; ks++) {
            uint32_t bh[4][2], bl[4][2];
#pragma unroll
            for (int ni = 0; ni < 4; ni++) {
                uint32_t rowb = (uint32_t)(wn * 32 + ni * 8) * APITCH + ks * 32;
                ldm2(bh[ni], sb + BH + rowb + boff);
                ldm2(bl[ni], sb + BL + rowb + boff);
            }
#pragma unroll
            for (int mi = 0; mi < 4; mi++) {
                uint32_t rowa = (uint32_t)(wm * 64 + mi * 16) * APITCH + ks * 32;
                uint32_t ah[4], al[4];
                ldm4(ah, sb + AH + rowa + aoff);
                ldm4(al, sb + AL + rowa + aoff);
#pragma unroll
                for (int ni = 0; ni < 4; ni++) {
                    mma16816(acc[mi][ni], ah, bh[ni]);
                    mma16816(acc[mi][ni], ah, bl[ni]);
                    mma16816(acc[mi][ni], al, bh[ni]);
                }
            }
        }
    }

    // ---- epilogue ----
    int g = lane >> 2, tg = lane & 3;
#pragma unroll
    for (int mi = 0; mi < 4; mi++) {
#pragma unroll
        for (int ni = 0; ni < 4; ni++) {
            int rg = row0 + wm * 64 + mi * 16 + g;
            int cg = col0 + wn * 32 + ni * 8 + tg * 2;
            float2 o0 = make_float2(acc[mi][ni][0], acc[mi][ni][1]);
            float2 o1 = make_float2(acc[mi][ni][2], acc[mi][ni][3]);
            *(float2*)(C + (size_t)rg * N + cg) = o0;
            *(float2*)(C + (size_t)(rg + 8) * N + cg) = o1;
        }
    }
}

// ---------------- per-head RMS norm of q and k (in place) ----------------
__global__ __launch_bounds__(256) void rms_kernel(float* __restrict__ qkv,
                                                  const float* __restrict__ qg,
                                                  const float* __restrict__ kg) {
    int w = (blockIdx.x * 256 + threadIdx.x) >> 5;
    int lane = threadIdx.x & 31;
    int qk  = w >> 17;
    int rem = w & 131071;
    int row = rem >> 4;
    int h   = rem & 15;
    float* p = qkv + (size_t)row * 3072 + qk * 1024 + h * DH + lane * 2;
    float2 v = *(float2*)p;
    float ss = v.x * v.x + v.y * v.y;
#pragma unroll
    for (int off = 16; off; off >>= 1) ss += __shfl_xor_sync(0xffffffffu, ss, off);
    float n = sqrtf(ss);
    float sc = 8.0f / fmaxf(n, 1e-12f);
    const float* g = (qk ? kg : qg) + h * DH + lane * 2;
    v.x *= sc * g[0];
    v.y *= sc * g[1];
    *(float2*)p = v;
}

// ---------------- fused flash attention (fp32) ----------------
#define KSTR 68
#define ATTN_SMEM (3 * 64 * KSTR * 4)

__global__ __launch_bounds__(256, 2) void attn_kernel(const float* __restrict__ qkv,
                                                      float* __restrict__ out) {
    extern __shared__ float smf[];
    float* Ks = smf;
    float* Vs = smf + 64 * KSTR;
    float* Ps = smf + 2 * 64 * KSTR;

    int bh = blockIdx.y;
    int b = bh >> 4, h = bh & 15;
    int i0 = blockIdx.x * 64;
    int tid = threadIdx.x;
    int ti = tid >> 2;
    int tx = tid & 3;

    const float* base  = qkv + (size_t)b * 1024 * 3072 + h * DH;
    const float* qbase = base;
    const float* kbase = base + 1024;
    const float* vbase = base + 2048;

    float4 q[16];
    {
        const float4* qp = (const float4*)(qbase + (size_t)(i0 + ti) * 3072);
#pragma unroll
        for (int d4 = 0; d4 < 16; d4++) q[d4] = qp[d4];
    }

    float4 O[4];
#pragma unroll
    for (int z = 0; z < 4; z++) O[z] = make_float4(0.f, 0.f, 0.f, 0.f);
    float m = -1e30f, l = 0.f;

    for (int jt = 0; jt < 16; jt++) {
        __syncthreads();
        int j0 = jt * 64;
        for (int t = tid; t < 1024; t += 256) {
            int r = t >> 4, c4 = (t & 15) * 4;
            *(float4*)(Ks + r * KSTR + c4) = *(const float4*)(kbase + (size_t)(j0 + r) * 3072 + c4);
            *(float4*)(Vs + r * KSTR + c4) = *(const float4*)(vbase + (size_t)(j0 + r) * 3072 + c4);
        }
        __syncthreads();

        float s[16];
#pragma unroll
        for (int jj = 0; jj < 16; jj++) {
            int j = jj * 4 + tx;
            const float4* kp = (const float4*)(Ks + j * KSTR);
            float4 a = make_float4(0.f, 0.f, 0.f, 0.f);
#pragma unroll
            for (int d4 = 0; d4 < 16; d4++) {
                float4 kv = kp[d4];
                a.x += q[d4].x * kv.x;
                a.y += q[d4].y * kv.y;
                a.z += q[d4].z * kv.z;
                a.w += q[d4].w * kv.w;
            }
            s[jj] = (a.x + a.y) + (a.z + a.w);
        }

        float mt = s[0];
#pragma unroll
        for (int jj = 1; jj < 16; jj++) mt = fmaxf(mt, s[jj]);
        mt = fmaxf(mt, __shfl_xor_sync(0xffffffffu, mt, 1));
        mt = fmaxf(mt, __shfl_xor_sync(0xffffffffu, mt, 2));
        float mnew = fmaxf(m, mt);
        float scale = __expf(m - mnew);
        float ls = 0.f;
#pragma unroll
        for (int jj = 0; jj < 16; jj++) {
            s[jj] = __expf(s[jj] - mnew);
            ls += s[jj];
        }
        ls += __shfl_xor_sync(0xffffffffu, ls, 1);
        ls += __shfl_xor_sync(0xffffffffu, ls, 2);
        l = l * scale + ls;
        m = mnew;

#pragma unroll
        for (int jj = 0; jj < 16; jj++) Ps[ti * KSTR + jj * 4 + tx] = s[jj];

#pragma unroll
        for (int z = 0; z < 4; z++) {
            O[z].x *= scale; O[z].y *= scale; O[z].z *= scale; O[z].w *= scale;
        }
        __syncthreads();

#pragma unroll 4
        for (int j = 0; j < 64; j++) {
            float pv = Ps[ti * KSTR + j];
            const float4* vp = (const float4*)(Vs + j * KSTR + tx * 16);
#pragma unroll
            for (int d4 = 0; d4 < 4; d4++) {
                float4 vv = vp[d4];
                O[d4].x += pv * vv.x;
                O[d4].y += pv * vv.y;
                O[d4].z += pv * vv.z;
                O[d4].w += pv * vv.w;
            }
        }
    }

    float inv = 1.0f / l;
    float* op = out + (size_t)(b * 1024 + i0 + ti) * 1024 + h * DH + tx * 16;
#pragma unroll
    for (int d4 = 0; d4 < 4; d4++) {
        float4 o = O[d4];
        o.x *= inv; o.y *= inv; o.z *= inv; o.w *= inv;
        *(float4*)(op + d4 * 4) = o;
    }
}

// ---------------- launch ----------------
extern "C" void kernel_launch(void* const* d_in, const int* in_sizes, int n_in,
                              void* d_out, int out_size) {
    const float* x     = (const float*)d_in[0];
    const float* ln_g  = (const float*)d_in[1];
    const float* qg    = (const float*)d_in[2];
    const float* kg    = (const float*)d_in[3];
    const float* wqkv  = (const float*)d_in[4];
    const float* wout  = (const float*)d_in[5];
    float* out = (float*)d_out;

    float *xn, *qkv, *ao, *wt, *wt2;
    cudaGetSymbolAddress((void**)&xn, g_xn);
    cudaGetSymbolAddress((void**)&qkv, g_qkv);
    cudaGetSymbolAddress((void**)&ao, g_ao);
    cudaGetSymbolAddress((void**)&wt, g_wt);
    cudaGetSymbolAddress((void**)&wt2, g_wt2);

    cudaFuncSetAttribute((const void*)attn_kernel,
                         cudaFuncAttributeMaxDynamicSharedMemorySize, ATTN_SMEM);

    ln_kernel<<<8192, 256>>>(x, ln_g, xn);
    transpose_kernel<<<dim3(3072 / 32, 1024 / 32), 256>>>(wqkv, wt, 1024, 3072);
    transpose_kernel<<<dim3(1024 / 32, 1024 / 32), 256>>>(wout, wt2, 1024, 1024);
    gemm_bf16<<<dim3(3072 / 128, 8192 / 128), 256>>>(xn, wt, qkv, 8192, 3072, 1024);
    rms_kernel<<<32768, 256>>>(qkv, qg, kg);
    attn_kernel<<<dim3(16, 128), 256, ATTN_SMEM>>>(qkv, ao);
    gemm_bf16<<<dim3(1024 / 128, 8192 / 128), 256>>>(ao, wt2, out, 8192, 1024, 1024);
}

// round 8
// speedup vs baseline: 4.5932x; 3.4977x over previous
#include <cuda_runtime.h>
#include <cuda_bf16.h>
#include <math.h>
#include <stdint.h>

// ---------------- scratch (no allocs allowed) ----------------
__device__ float g_xn[8192 * 1024];    // layernormed x
__device__ float g_qkv[8192 * 3072];   // qkv projection (q,k normed in place)
__device__ float g_ao[8192 * 1024];    // attention out
__device__ float g_wt[3072 * 1024];    // w_qkv transposed  [N][K]
__device__ float g_wt2[1024 * 1024];   // w_out transposed  [N][K]

#define DIMM 1024
#define HEADS 16
#define DH 64

// ================= helpers =================
static __device__ __forceinline__ uint32_t s2u(const void* p) {
    uint32_t a;
    asm("{ .reg .u64 t; cvta.to.shared.u64 t, %1; cvt.u32.u64 %0, t; }" : "=r"(a) : "l"(p));
    return a;
}
static __device__ __forceinline__ void ldm4(uint32_t* r, uint32_t addr) {
    asm volatile("ldmatrix.sync.aligned.m8n8.x4.shared.b16 {%0,%1,%2,%3}, [%4];"
                 : "=r"(r[0]), "=r"(r[1]), "=r"(r[2]), "=r"(r[3]) : "r"(addr));
}
static __device__ __forceinline__ void ldm2(uint32_t* r, uint32_t addr) {
    asm volatile("ldmatrix.sync.aligned.m8n8.x2.shared.b16 {%0,%1}, [%2];"
                 : "=r"(r[0]), "=r"(r[1]) : "r"(addr));
}
static __device__ __forceinline__ void ldm2t(uint32_t* r, uint32_t addr) {
    asm volatile("ldmatrix.sync.aligned.m8n8.x2.trans.shared.b16 {%0,%1}, [%2];"
                 : "=r"(r[0]), "=r"(r[1]) : "r"(addr));
}
static __device__ __forceinline__ void mma16816(float* c, const uint32_t* a, const uint32_t* b) {
    asm volatile(
        "mma.sync.aligned.m16n8k16.row.col.f32.bf16.bf16.f32 "
        "{%0,%1,%2,%3}, {%4,%5,%6,%7}, {%8,%9}, {%0,%1,%2,%3};"
        : "+f"(c[0]), "+f"(c[1]), "+f"(c[2]), "+f"(c[3])
        : "r"(a[0]), "r"(a[1]), "r"(a[2]), "r"(a[3]), "r"(b[0]), "r"(b[1]));
}
static __device__ __forceinline__ uint32_t packbf(__nv_bfloat16 a, __nv_bfloat16 b) {
    return (uint32_t)__bfloat16_as_ushort(a) | ((uint32_t)__bfloat16_as_ushort(b) << 16);
}
// split float pair into (hi bf16x2, lo bf16x2)
static __device__ __forceinline__ void split2(float x, float y, uint32_t& hi, uint32_t& lo) {
    __nv_bfloat16 hx = __float2bfloat16_rn(x);
    __nv_bfloat16 hy = __float2bfloat16_rn(y);
    hi = packbf(hx, hy);
    lo = packbf(__float2bfloat16_rn(x - __bfloat162float(hx)),
                __float2bfloat16_rn(y - __bfloat162float(hy)));
}

// ---------------- LayerNorm ----------------
__global__ __launch_bounds__(256) void ln_kernel(const float* __restrict__ x,
                                                 const float* __restrict__ g,
                                                 float* __restrict__ o) {
    int row = blockIdx.x;
    int tid = threadIdx.x;
    const float* xr = x + (size_t)row * DIMM;
    float4 v = *(const float4*)(xr + tid * 4);
    float s  = v.x + v.y + v.z + v.w;
    float ss = v.x * v.x + v.y * v.y + v.z * v.z + v.w * v.w;
#pragma unroll
    for (int off = 16; off; off >>= 1) {
        s  += __shfl_xor_sync(0xffffffffu, s, off);
        ss += __shfl_xor_sync(0xffffffffu, ss, off);
    }
    __shared__ float rs[8], rss[8];
    __shared__ float mu_s, rstd_s;
    int w = tid >> 5, lane = tid & 31;
    if (!lane) { rs[w] = s; rss[w] = ss; }
    __syncthreads();
    if (tid == 0) {
        float S = 0.f, SS = 0.f;
#pragma unroll
        for (int i = 0; i < 8; i++) { S += rs[i]; SS += rss[i]; }
        float mu  = S * (1.0f / DIMM);
        float var = SS * (1.0f / DIMM) - mu * mu;
        mu_s = mu;
        rstd_s = rsqrtf(var + 1e-5f);
    }
    __syncthreads();
    float mu = mu_s, r = rstd_s;
    float4 gv = *(const float4*)(g + tid * 4);
    float4 ov;
    ov.x = (v.x - mu) * r * gv.x;
    ov.y = (v.y - mu) * r * gv.y;
    ov.z = (v.z - mu) * r * gv.z;
    ov.w = (v.w - mu) * r * gv.w;
    *(float4*)(o + (size_t)row * DIMM + tid * 4) = ov;
}

// ---------------- transpose ----------------
__global__ __launch_bounds__(256) void transpose_kernel(const float* __restrict__ in,
                                                        float* __restrict__ out,
                                                        int R, int C) {
    __shared__ float t[32][33];
    int bx = blockIdx.x * 32;
    int by = blockIdx.y * 32;
    int tx = threadIdx.x & 31, ty = threadIdx.x >> 5;
#pragma unroll
    for (int j = 0; j < 32; j += 8)
        t[ty + j][tx] = in[(size_t)(by + ty + j) * C + bx + tx];
    __syncthreads();
#pragma unroll
    for (int j = 0; j < 32; j += 8)
        out[(size_t)(bx + ty + j) * R + by + tx] = t[tx][ty + j];
}

// ---------------- bf16x2-split tensor-core GEMM ----------------
#define APITCH 80

__global__ __launch_bounds__(256, 2) void gemm_bf16(const float* __restrict__ A,
                                                    const float* __restrict__ Bt,
                                                    float* __restrict__ C,
                                                    int M, int N, int K) {
    __shared__ __align__(1024) unsigned char sm[4 * 128 * APITCH];
    uint32_t sb = s2u(sm);
    const uint32_t AH = 0, AL = 128 * APITCH, BH = 2 * 128 * APITCH, BL = 3 * 128 * APITCH;

    int tid = threadIdx.x;
    int lane = tid & 31;
    int w = tid >> 5;
    int wm = w & 1;
    int wn = w >> 1;
    int row0 = blockIdx.y * 128, col0 = blockIdx.x * 128;

    float acc[4][4][4];
#pragma unroll
    for (int i = 0; i < 4; i++)
#pragma unroll
        for (int j = 0; j < 4; j++)
#pragma unroll
            for (int q = 0; q < 4; q++) acc[i][j][q] = 0.f;

    uint32_t aoff = (uint32_t)(lane & 15) * APITCH + (uint32_t)(lane >> 4) * 16;
    uint32_t l16 = lane & 15;
    uint32_t boff = (l16 & 7) * APITCH + ((l16 >> 3) & 1) * 16;

    const int nchunk = K >> 5;
    for (int c = 0; c < nchunk; c++) {
        __syncthreads();
#pragma unroll
        for (int it = 0; it < 4; it++) {
            int idx = tid + it * 256;
            int r = idx >> 3;
            int f4 = idx & 7;
            uint32_t so = (uint32_t)r * APITCH + (uint32_t)f4 * 8;

            float4 va = *(const float4*)(A + (size_t)(row0 + r) * K + c * 32 + f4 * 4);
            uint2 hi, lo;
            split2(va.x, va.y, hi.x, lo.x);
            split2(va.z, va.w, hi.y, lo.y);
            *(uint2*)(sm + AH + so) = hi;
            *(uint2*)(sm + AL + so) = lo;

            float4 vb = *(const float4*)(Bt + (size_t)(col0 + r) * K + c * 32 + f4 * 4);
            split2(vb.x, vb.y, hi.x, lo.x);
            split2(vb.z, vb.w, hi.y, lo.y);
            *(uint2*)(sm + BH + so) = hi;
            *(uint2*)(sm + BL + so) = lo;
        }
        __syncthreads();

#pragma unroll
        for (int ks = 0; ks < 2; ks++) {
            uint32_t bh[4][2], bl[4][2];
#pragma unroll
            for (int ni = 0; ni < 4; ni++) {
                uint32_t rowb = (uint32_t)(wn * 32 + ni * 8) * APITCH + ks * 32;
                ldm2(bh[ni], sb + BH + rowb + boff);
                ldm2(bl[ni], sb + BL + rowb + boff);
            }
#pragma unroll
            for (int mi = 0; mi < 4; mi++) {
                uint32_t rowa = (uint32_t)(wm * 64 + mi * 16) * APITCH + ks * 32;
                uint32_t ah[4], al[4];
                ldm4(ah, sb + AH + rowa + aoff);
                ldm4(al, sb + AL + rowa + aoff);
#pragma unroll
                for (int ni = 0; ni < 4; ni++) {
                    mma16816(acc[mi][ni], ah, bh[ni]);
                    mma16816(acc[mi][ni], ah, bl[ni]);
                    mma16816(acc[mi][ni], al, bh[ni]);
                }
            }
        }
    }

    int g = lane >> 2, tg = lane & 3;
#pragma unroll
    for (int mi = 0; mi < 4; mi++) {
#pragma unroll
        for (int ni = 0; ni < 4; ni++) {
            int rg = row0 + wm * 64 + mi * 16 + g;
            int cg = col0 + wn * 32 + ni * 8 + tg * 2;
            float2 o0 = make_float2(acc[mi][ni][0], acc[mi][ni][1]);
            float2 o1 = make_float2(acc[mi][ni][2], acc[mi][ni][3]);
            *(float2*)(C + (size_t)rg * N + cg) = o0;
            *(float2*)(C + (size_t)(rg + 8) * N + cg) = o1;
        }
    }
}

// ---------------- per-head RMS norm of q and k (in place) ----------------
__global__ __launch_bounds__(256) void rms_kernel(float* __restrict__ qkv,
                                                  const float* __restrict__ qg,
                                                  const float* __restrict__ kg) {
    int w = (blockIdx.x * 256 + threadIdx.x) >> 5;
    int lane = threadIdx.x & 31;
    int qk  = w >> 17;
    int rem = w & 131071;
    int row = rem >> 4;
    int h   = rem & 15;
    float* p = qkv + (size_t)row * 3072 + qk * 1024 + h * DH + lane * 2;
    float2 v = *(float2*)p;
    float ss = v.x * v.x + v.y * v.y;
#pragma unroll
    for (int off = 16; off; off >>= 1) ss += __shfl_xor_sync(0xffffffffu, ss, off);
    float n = sqrtf(ss);
    float sc = 8.0f / fmaxf(n, 1e-12f);
    const float* g = (qk ? kg : qg) + h * DH + lane * 2;
    v.x *= sc * g[0];
    v.y *= sc * g[1];
    *(float2*)p = v;
}

// ---------------- flash attention on mma.sync bf16 (split hi/lo) ----------------
// CTA: 128 q rows of one (b,h). 8 warps x 16 rows. j-tiles of 64 keys.
// smem: Qh/Ql [128][72] bf16, Kh/Kl/Vh/Vl [64][72] bf16; pitch 144B.
#define FPIT 144
#define SQH 0
#define SQL (128 * FPIT)
#define SKH (2 * 128 * FPIT)
#define SKL (SKH + 64 * FPIT)
#define SVH (SKL + 64 * FPIT)
#define SVL (SVH + 64 * FPIT)
#define ATTN_SMEM (SVL + 64 * FPIT)   // 73728 B

__global__ __launch_bounds__(256, 2) void attn_mma(const float* __restrict__ qkv,
                                                   float* __restrict__ out) {
    extern __shared__ unsigned char smb[];
    uint32_t sb = s2u(smb);

    int tid = threadIdx.x;
    int lane = tid & 31;
    int w = tid >> 5;
    int bh = blockIdx.y;
    int b = bh >> 4, h = bh & 15;
    int i0 = blockIdx.x * 128;

    const float* base  = qkv + (size_t)b * 1024 * 3072 + h * DH;
    const float* qbase = base;
    const float* kbase = base + 1024;
    const float* vbase = base + 2048;

    // ---- load Q tile (128 x 64) split hi/lo ----
#pragma unroll
    for (int it = 0; it < 8; it++) {
        int idx = tid + it * 256;       // 0..2047
        int r = idx >> 4;               // 0..127
        int f4 = idx & 15;              // float4 within row
        float4 v = *(const float4*)(qbase + (size_t)(i0 + r) * 3072 + f4 * 4);
        uint2 hi, lo;
        split2(v.x, v.y, hi.x, lo.x);
        split2(v.z, v.w, hi.y, lo.y);
        uint32_t so = (uint32_t)r * FPIT + (uint32_t)f4 * 8;
        *(uint2*)(smb + SQH + so) = hi;
        *(uint2*)(smb + SQL + so) = lo;
    }

    float m0 = -1e30f, m1 = -1e30f, l0 = 0.f, l1 = 0.f;
    float O[8][4];
#pragma unroll
    for (int nd = 0; nd < 8; nd++)
#pragma unroll
        for (int q = 0; q < 4; q++) O[nd][q] = 0.f;

    uint32_t aoff = (uint32_t)(lane & 15) * FPIT + (uint32_t)(lane >> 4) * 16;
    uint32_t koff = (uint32_t)(lane & 7) * FPIT + (uint32_t)((lane >> 3) & 1) * 16;
    uint32_t voff = (uint32_t)(lane & 15) * FPIT;

    for (int jt = 0; jt < 16; jt++) {
        __syncthreads();
        int j0 = jt * 64;
        // ---- load K,V tiles (64 x 64 each), split hi/lo ----
#pragma unroll
        for (int it = 0; it < 8; it++) {
            int idx = tid + (it & 3) * 256;  // 0..1023
            int r = idx >> 4;                // 0..63
            int f4 = idx & 15;
            const float* src = (it < 4 ? kbase : vbase) + (size_t)(j0 + r) * 3072 + f4 * 4;
            float4 v = *(const float4*)src;
            uint2 hi, lo;
            split2(v.x, v.y, hi.x, lo.x);
            split2(v.z, v.w, hi.y, lo.y);
            uint32_t so = (uint32_t)r * FPIT + (uint32_t)f4 * 8;
            uint32_t dh = (it < 4) ? SKH : SVH;
            uint32_t dl = (it < 4) ? SKL : SVL;
            *(uint2*)(smb + dh + so) = hi;
            *(uint2*)(smb + dl + so) = lo;
        }
        __syncthreads();

        // ---- S = Q K^T (128x64 per CTA, 16x64 per warp) ----
        float S[8][4];
#pragma unroll
        for (int jj = 0; jj < 8; jj++)
#pragma unroll
            for (int q = 0; q < 4; q++) S[jj][q] = 0.f;

#pragma unroll
        for (int ks = 0; ks < 4; ks++) {
            uint32_t qh[4], ql[4];
            uint32_t qa = (uint32_t)(w * 16) * FPIT + ks * 32 + aoff;
            ldm4(qh, sb + SQH + qa);
            ldm4(ql, sb + SQL + qa);
#pragma unroll
            for (int jj = 0; jj < 8; jj++) {
                uint32_t kh[2], kl[2];
                uint32_t ka = (uint32_t)(jj * 8) * FPIT + ks * 32 + koff;
                ldm2(kh, sb + SKH + ka);
                ldm2(kl, sb + SKL + ka);
                mma16816(S[jj], qh, kh);
                mma16816(S[jj], qh, kl);
                mma16816(S[jj], ql, kh);
            }
        }

        // ---- online softmax (rows r0=lane/4, r1=r0+8) ----
        float mt0 = S[0][0], mt1 = S[0][2];
#pragma unroll
        for (int jj = 0; jj < 8; jj++) {
            mt0 = fmaxf(mt0, fmaxf(S[jj][0], S[jj][1]));
            mt1 = fmaxf(mt1, fmaxf(S[jj][2], S[jj][3]));
        }
        mt0 = fmaxf(mt0, __shfl_xor_sync(0xffffffffu, mt0, 1));
        mt0 = fmaxf(mt0, __shfl_xor_sync(0xffffffffu, mt0, 2));
        mt1 = fmaxf(mt1, __shfl_xor_sync(0xffffffffu, mt1, 1));
        mt1 = fmaxf(mt1, __shfl_xor_sync(0xffffffffu, mt1, 2));
        float mn0 = fmaxf(m0, mt0), mn1 = fmaxf(m1, mt1);
        float sc0 = __expf(m0 - mn0), sc1 = __expf(m1 - mn1);

        uint32_t Ph[8][2], Pl[8][2];
        float ls0 = 0.f, ls1 = 0.f;
#pragma unroll
        for (int jj = 0; jj < 8; jj++) {
            float p0 = __expf(S[jj][0] - mn0);
            float p1 = __expf(S[jj][1] - mn0);
            float p2 = __expf(S[jj][2] - mn1);
            float p3 = __expf(S[jj][3] - mn1);
            ls0 += p0 + p1;
            ls1 += p2 + p3;
            split2(p0, p1, Ph[jj][0], Pl[jj][0]);
            split2(p2, p3, Ph[jj][1], Pl[jj][1]);
        }
        ls0 += __shfl_xor_sync(0xffffffffu, ls0, 1);
        ls0 += __shfl_xor_sync(0xffffffffu, ls0, 2);
        ls1 += __shfl_xor_sync(0xffffffffu, ls1, 1);
        ls1 += __shfl_xor_sync(0xffffffffu, ls1, 2);
        l0 = l0 * sc0 + ls0;
        l1 = l1 * sc1 + ls1;
        m0 = mn0;
        m1 = mn1;

#pragma unroll
        for (int nd = 0; nd < 8; nd++) {
            O[nd][0] *= sc0; O[nd][1] *= sc0;
            O[nd][2] *= sc1; O[nd][3] *= sc1;
        }

        // ---- O += P V ----
#pragma unroll
        for (int kk = 0; kk < 4; kk++) {
            uint32_t ah[4] = {Ph[2 * kk][0], Ph[2 * kk][1], Ph[2 * kk + 1][0], Ph[2 * kk + 1][1]};
            uint32_t al[4] = {Pl[2 * kk][0], Pl[2 * kk][1], Pl[2 * kk + 1][0], Pl[2 * kk + 1][1]};
#pragma unroll
            for (int nd = 0; nd < 8; nd++) {
                uint32_t vh[2], vl[2];
                uint32_t va = (uint32_t)(kk * 16) * FPIT + nd * 16 + voff;
                ldm2t(vh, sb + SVH + va);
                ldm2t(vl, sb + SVL + va);
                mma16816(O[nd], ah, vh);
                mma16816(O[nd], ah, vl);
                mma16816(O[nd], al, vh);
            }
        }
    }

    // ---- epilogue: divide by l, write to out[b*1024+n][h*64+d] ----
    float inv0 = 1.0f / l0, inv1 = 1.0f / l1;
    int r0 = b * 1024 + i0 + w * 16 + (lane >> 2);
    int cg = h * DH + (lane & 3) * 2;
#pragma unroll
    for (int nd = 0; nd < 8; nd++) {
        float2 o0 = make_float2(O[nd][0] * inv0, O[nd][1] * inv0);
        float2 o1 = make_float2(O[nd][2] * inv1, O[nd][3] * inv1);
        *(float2*)(out + (size_t)r0 * 1024 + cg + nd * 8) = o0;
        *(float2*)(out + (size_t)(r0 + 8) * 1024 + cg + nd * 8) = o1;
    }
}

// ---------------- launch ----------------
extern "C" void kernel_launch(void* const* d_in, const int* in_sizes, int n_in,
                              void* d_out, int out_size) {
    const float* x     = (const float*)d_in[0];
    const float* ln_g  = (const float*)d_in[1];
    const float* qg    = (const float*)d_in[2];
    const float* kg    = (const float*)d_in[3];
    const float* wqkv  = (const float*)d_in[4];
    const float* wout  = (const float*)d_in[5];
    float* out = (float*)d_out;

    float *xn, *qkv, *ao, *wt, *wt2;
    cudaGetSymbolAddress((void**)&xn, g_xn);
    cudaGetSymbolAddress((void**)&qkv, g_qkv);
    cudaGetSymbolAddress((void**)&ao, g_ao);
    cudaGetSymbolAddress((void**)&wt, g_wt);
    cudaGetSymbolAddress((void**)&wt2, g_wt2);

    cudaFuncSetAttribute((const void*)attn_mma,
                         cudaFuncAttributeMaxDynamicSharedMemorySize, ATTN_SMEM);

    ln_kernel<<<8192, 256>>>(x, ln_g, xn);
    transpose_kernel<<<dim3(3072 / 32, 1024 / 32), 256>>>(wqkv, wt, 1024, 3072);
    transpose_kernel<<<dim3(1024 / 32, 1024 / 32), 256>>>(wout, wt2, 1024, 1024);
    gemm_bf16<<<dim3(3072 / 128, 8192 / 128), 256>>>(xn, wt, qkv, 8192, 3072, 1024);
    rms_kernel<<<32768, 256>>>(qkv, qg, kg);
    attn_mma<<<dim3(8, 128), 256, ATTN_SMEM>>>(qkv, ao);
    gemm_bf16<<<dim3(1024 / 128, 8192 / 128), 256>>>(ao, wt2, out, 8192, 1024, 1024);
}

// round 9
// speedup vs baseline: 4.7672x; 1.0379x over previous
#include <cuda_runtime.h>
#include <cuda_bf16.h>
#include <math.h>
#include <stdint.h>

// ---------------- scratch (no allocs allowed) ----------------
__device__ float g_qkv[8192 * 3072];                  // qkv projection fp32
__device__ __nv_bfloat16 g_xnh[8192 * 1024];          // layernormed x, split
__device__ __nv_bfloat16 g_xnl[8192 * 1024];
__device__ __nv_bfloat16 g_qh[8192 * 3072];           // split qkv (q,k rms-normed)
__device__ __nv_bfloat16 g_ql[8192 * 3072];
__device__ __nv_bfloat16 g_aoh[8192 * 1024];          // attention out, split
__device__ __nv_bfloat16 g_aol[8192 * 1024];
__device__ __nv_bfloat16 g_wth[3072 * 1024];          // w_qkv^T split [N][K]
__device__ __nv_bfloat16 g_wtl[3072 * 1024];
__device__ __nv_bfloat16 g_w2h[1024 * 1024];          // w_out^T split [N][K]
__device__ __nv_bfloat16 g_w2l[1024 * 1024];

#define DIMM 1024
#define DH 64

// ================= helpers =================
static __device__ __forceinline__ uint32_t s2u(const void* p) {
    uint32_t a;
    asm("{ .reg .u64 t; cvta.to.shared.u64 t, %1; cvt.u32.u64 %0, t; }" : "=r"(a) : "l"(p));
    return a;
}
static __device__ __forceinline__ void ldm4(uint32_t* r, uint32_t addr) {
    asm volatile("ldmatrix.sync.aligned.m8n8.x4.shared.b16 {%0,%1,%2,%3}, [%4];"
                 : "=r"(r[0]), "=r"(r[1]), "=r"(r[2]), "=r"(r[3]) : "r"(addr));
}
static __device__ __forceinline__ void ldm2(uint32_t* r, uint32_t addr) {
    asm volatile("ldmatrix.sync.aligned.m8n8.x2.shared.b16 {%0,%1}, [%2];"
                 : "=r"(r[0]), "=r"(r[1]) : "r"(addr));
}
static __device__ __forceinline__ void ldm2t(uint32_t* r, uint32_t addr) {
    asm volatile("ldmatrix.sync.aligned.m8n8.x2.trans.shared.b16 {%0,%1}, [%2];"
                 : "=r"(r[0]), "=r"(r[1]) : "r"(addr));
}
static __device__ __forceinline__ void mma16816(float* c, const uint32_t* a, const uint32_t* b) {
    asm volatile(
        "mma.sync.aligned.m16n8k16.row.col.f32.bf16.bf16.f32 "
        "{%0,%1,%2,%3}, {%4,%5,%6,%7}, {%8,%9}, {%0,%1,%2,%3};"
        : "+f"(c[0]), "+f"(c[1]), "+f"(c[2]), "+f"(c[3])
        : "r"(a[0]), "r"(a[1]), "r"(a[2]), "r"(a[3]), "r"(b[0]), "r"(b[1]));
}
static __device__ __forceinline__ uint32_t packbf(__nv_bfloat16 a, __nv_bfloat16 b) {
    return (uint32_t)__bfloat16_as_ushort(a) | ((uint32_t)__bfloat16_as_ushort(b) << 16);
}
static __device__ __forceinline__ void split2(float x, float y, uint32_t& hi, uint32_t& lo) {
    __nv_bfloat16 hx = __float2bfloat16_rn(x);
    __nv_bfloat16 hy = __float2bfloat16_rn(y);
    hi = packbf(hx, hy);
    lo = packbf(__float2bfloat16_rn(x - __bfloat162float(hx)),
                __float2bfloat16_rn(y - __bfloat162float(hy)));
}
static __device__ __forceinline__ void cpa16(uint32_t dst, const void* src) {
    asm volatile("cp.async.cg.shared.global [%0], [%1], 16;" :: "r"(dst), "l"(src));
}
static __device__ __forceinline__ void cpa_commit() {
    asm volatile("cp.async.commit_group;" ::: "memory");
}

// ---------------- LayerNorm -> split bf16 ----------------
__global__ __launch_bounds__(256) void ln_kernel(const float* __restrict__ x,
                                                 const float* __restrict__ g,
                                                 __nv_bfloat16* __restrict__ oh,
                                                 __nv_bfloat16* __restrict__ ol) {
    int row = blockIdx.x;
    int tid = threadIdx.x;
    const float* xr = x + (size_t)row * DIMM;
    float4 v = *(const float4*)(xr + tid * 4);
    float s  = v.x + v.y + v.z + v.w;
    float ss = v.x * v.x + v.y * v.y + v.z * v.z + v.w * v.w;
#pragma unroll
    for (int off = 16; off; off >>= 1) {
        s  += __shfl_xor_sync(0xffffffffu, s, off);
        ss += __shfl_xor_sync(0xffffffffu, ss, off);
    }
    __shared__ float rs[8], rss[8];
    __shared__ float mu_s, rstd_s;
    int w = tid >> 5, lane = tid & 31;
    if (!lane) { rs[w] = s; rss[w] = ss; }
    __syncthreads();
    if (tid == 0) {
        float S = 0.f, SS = 0.f;
#pragma unroll
        for (int i = 0; i < 8; i++) { S += rs[i]; SS += rss[i]; }
        float mu  = S * (1.0f / DIMM);
        float var = SS * (1.0f / DIMM) - mu * mu;
        mu_s = mu;
        rstd_s = rsqrtf(var + 1e-5f);
    }
    __syncthreads();
    float mu = mu_s, r = rstd_s;
    float4 gv = *(const float4*)(g + tid * 4);
    float a0 = (v.x - mu) * r * gv.x;
    float a1 = (v.y - mu) * r * gv.y;
    float a2 = (v.z - mu) * r * gv.z;
    float a3 = (v.w - mu) * r * gv.w;
    uint2 hi, lo;
    split2(a0, a1, hi.x, lo.x);
    split2(a2, a3, hi.y, lo.y);
    size_t off = (size_t)row * DIMM + tid * 4;
    *(uint2*)(oh + off) = hi;
    *(uint2*)(ol + off) = lo;
}

// ---------------- transpose + split: out[C][R] = split(in[R][C]^T) ----------------
__global__ __launch_bounds__(256) void transpose_split(const float* __restrict__ in,
                                                       __nv_bfloat16* __restrict__ oh,
                                                       __nv_bfloat16* __restrict__ ol,
                                                       int R, int C) {
    __shared__ float t[32][33];
    int bx = blockIdx.x * 32;
    int by = blockIdx.y * 32;
    int tx = threadIdx.x & 31, ty = threadIdx.x >> 5;
#pragma unroll
    for (int j = 0; j < 32; j += 8)
        t[ty + j][tx] = in[(size_t)(by + ty + j) * C + bx + tx];
    __syncthreads();
#pragma unroll
    for (int j = 0; j < 32; j += 8) {
        float v = t[tx][ty + j];
        __nv_bfloat16 hb = __float2bfloat16_rn(v);
        size_t off = (size_t)(bx + ty + j) * R + by + tx;
        oh[off] = hb;
        ol[off] = __float2bfloat16_rn(v - __bfloat162float(hb));
    }
}

// ---------------- double-buffered split-bf16 tensor-core GEMM ----------------
// C[M,N] = (Ah+Al)[M,K] @ (Bh+Bl)[N,K]^T, 3-term product.
// 128x128 CTA tile, BK=32, 2-stage cp.async pipeline, 8 warps (2x4).
#define GP 80
#define STAGE_B (4 * 128 * GP)        // 40960
#define GEMM_SMEM (2 * STAGE_B)       // 81920

__global__ __launch_bounds__(256, 2) void gemm_split(const __nv_bfloat16* __restrict__ Ah,
                                                     const __nv_bfloat16* __restrict__ Al,
                                                     const __nv_bfloat16* __restrict__ Bh,
                                                     const __nv_bfloat16* __restrict__ Bl,
                                                     float* __restrict__ C,
                                                     int M, int N, int K) {
    extern __shared__ unsigned char smg[];
    uint32_t sb = s2u(smg);
    const uint32_t AH = 0, AL = 128 * GP, BHo = 2 * 128 * GP, BLo = 3 * 128 * GP;

    int tid = threadIdx.x;
    int lane = tid & 31;
    int w = tid >> 5;
    int wm = w & 1;
    int wn = w >> 1;
    int row0 = blockIdx.y * 128, col0 = blockIdx.x * 128;

    const __nv_bfloat16* srcs[4] = {Ah + (size_t)row0 * K, Al + (size_t)row0 * K,
                                    Bh + (size_t)col0 * K, Bl + (size_t)col0 * K};

    float acc[4][4][4];
#pragma unroll
    for (int i = 0; i < 4; i++)
#pragma unroll
        for (int j = 0; j < 4; j++)
#pragma unroll
            for (int q = 0; q < 4; q++) acc[i][j][q] = 0.f;

    uint32_t aoff = (uint32_t)(lane & 15) * GP + (uint32_t)(lane >> 4) * 16;
    uint32_t l16 = lane & 15;
    uint32_t boff = (l16 & 7) * GP + ((l16 >> 3) & 1) * 16;

    const int nchunk = K >> 5;

    // preload chunk 0 into stage 0
#pragma unroll
    for (int it = 0; it < 8; it++) {
        int tile = it >> 1;
        int rem = (it & 1) * 256 + tid;
        int r = rem >> 2, f4 = rem & 3;
        cpa16(sb + tile * (128 * GP) + (uint32_t)r * GP + f4 * 16,
              srcs[tile] + (size_t)r * K + f4 * 8);
    }
    cpa_commit();

    for (int c = 0; c < nchunk; c++) {
        if (c + 1 < nchunk) {
            uint32_t st = sb + ((c + 1) & 1) * STAGE_B;
#pragma unroll
            for (int it = 0; it < 8; it++) {
                int tile = it >> 1;
                int rem = (it & 1) * 256 + tid;
                int r = rem >> 2, f4 = rem & 3;
                cpa16(st + tile * (128 * GP) + (uint32_t)r * GP + f4 * 16,
                      srcs[tile] + (size_t)r * K + (c + 1) * 32 + f4 * 8);
            }
            cpa_commit();
            asm volatile("cp.async.wait_group 1;" ::: "memory");
        } else {
            asm volatile("cp.async.wait_group 0;" ::: "memory");
        }
        __syncthreads();

        uint32_t st = sb + (c & 1) * STAGE_B;
#pragma unroll
        for (int ks = 0; ks < 2; ks++) {
            uint32_t bh[4][2], bl[4][2];
#pragma unroll
            for (int ni = 0; ni < 4; ni++) {
                uint32_t rowb = (uint32_t)(wn * 32 + ni * 8) * GP + ks * 32;
                ldm2(bh[ni], st + BHo + rowb + boff);
                ldm2(bl[ni], st + BLo + rowb + boff);
            }
#pragma unroll
            for (int mi = 0; mi < 4; mi++) {
                uint32_t rowa = (uint32_t)(wm * 64 + mi * 16) * GP + ks * 32;
                uint32_t ah[4], al[4];
                ldm4(ah, st + AH + rowa + aoff);
                ldm4(al, st + AL + rowa + aoff);
#pragma unroll
                for (int ni = 0; ni < 4; ni++) {
                    mma16816(acc[mi][ni], ah, bh[ni]);
                    mma16816(acc[mi][ni], ah, bl[ni]);
                    mma16816(acc[mi][ni], al, bh[ni]);
                }
            }
        }
        __syncthreads();
    }

    int g = lane >> 2, tg = lane & 3;
#pragma unroll
    for (int mi = 0; mi < 4; mi++) {
#pragma unroll
        for (int ni = 0; ni < 4; ni++) {
            int rg = row0 + wm * 64 + mi * 16 + g;
            int cg = col0 + wn * 32 + ni * 8 + tg * 2;
            float2 o0 = make_float2(acc[mi][ni][0], acc[mi][ni][1]);
            float2 o1 = make_float2(acc[mi][ni][2], acc[mi][ni][3]);
            *(float2*)(C + (size_t)rg * N + cg) = o0;
            *(float2*)(C + (size_t)(rg + 8) * N + cg) = o1;
        }
    }
}

// ---------------- RMS norm q,k + split all of qkv to bf16 hi/lo ----------------
__global__ __launch_bounds__(256) void rms_split(const float* __restrict__ qkv,
                                                 const float* __restrict__ qg,
                                                 const float* __restrict__ kg,
                                                 __nv_bfloat16* __restrict__ oh,
                                                 __nv_bfloat16* __restrict__ ol) {
    int w = (blockIdx.x * 256 + threadIdx.x) >> 5;   // 0 .. 393215
    int lane = threadIdx.x & 31;
    int qk  = w >> 17;          // 0=q, 1=k, 2=v
    int rem = w & 131071;
    int row = rem >> 4;
    int h   = rem & 15;
    size_t off = (size_t)row * 3072 + qk * 1024 + h * DH + lane * 2;
    float2 v = *(const float2*)(qkv + off);
    if (qk < 2) {
        float ss = v.x * v.x + v.y * v.y;
#pragma unroll
        for (int o = 16; o; o >>= 1) ss += __shfl_xor_sync(0xffffffffu, ss, o);
        float sc = 8.0f / fmaxf(sqrtf(ss), 1e-12f);
        const float* g = (qk ? kg : qg) + h * DH + lane * 2;
        v.x *= sc * g[0];
        v.y *= sc * g[1];
    }
    uint32_t hi, lo;
    split2(v.x, v.y, hi, lo);
    *(uint32_t*)(oh + off) = hi;
    *(uint32_t*)(ol + off) = lo;
}

// ---------------- flash attention on mma.sync bf16 (pre-split inputs) ----------------
#define FPIT 144
#define SQH 0
#define SQL (128 * FPIT)
#define SKH (2 * 128 * FPIT)
#define SKL (SKH + 64 * FPIT)
#define SVH (SKL + 64 * FPIT)
#define SVL (SVH + 64 * FPIT)
#define ATTN_SMEM (SVL + 64 * FPIT)   // 73728 B

__global__ __launch_bounds__(256, 2) void attn_mma(const __nv_bfloat16* __restrict__ qh,
                                                   const __nv_bfloat16* __restrict__ ql,
                                                   __nv_bfloat16* __restrict__ aoh,
                                                   __nv_bfloat16* __restrict__ aol) {
    extern __shared__ unsigned char smb[];
    uint32_t sb = s2u(smb);

    int tid = threadIdx.x;
    int lane = tid & 31;
    int w = tid >> 5;
    int bh = blockIdx.y;
    int b = bh >> 4, h = bh & 15;
    int i0 = blockIdx.x * 128;

    size_t base = (size_t)b * 1024 * 3072 + h * DH;
    const __nv_bfloat16* qbh = qh + base;
    const __nv_bfloat16* qbl = ql + base;
    const __nv_bfloat16* kbh = qh + base + 1024;
    const __nv_bfloat16* kbl = ql + base + 1024;
    const __nv_bfloat16* vbh = qh + base + 2048;
    const __nv_bfloat16* vbl = ql + base + 2048;

    // ---- load Q tile (128 x 64) from pre-split ----
#pragma unroll
    for (int it = 0; it < 8; it++) {
        int idx = tid + it * 256;       // 0..2047
        int r = idx >> 4;               // 0..127
        int f4 = idx & 15;              // 4-elem chunk
        size_t go = (size_t)(i0 + r) * 3072 + f4 * 4;
        uint32_t so = (uint32_t)r * FPIT + (uint32_t)f4 * 8;
        *(uint2*)(smb + SQH + so) = *(const uint2*)(qbh + go);
        *(uint2*)(smb + SQL + so) = *(const uint2*)(qbl + go);
    }

    float m0 = -1e30f, m1 = -1e30f, l0 = 0.f, l1 = 0.f;
    float O[8][4];
#pragma unroll
    for (int nd = 0; nd < 8; nd++)
#pragma unroll
        for (int q = 0; q < 4; q++) O[nd][q] = 0.f;

    uint32_t aoff = (uint32_t)(lane & 15) * FPIT + (uint32_t)(lane >> 4) * 16;
    uint32_t koff = (uint32_t)(lane & 7) * FPIT + (uint32_t)((lane >> 3) & 1) * 16;
    uint32_t voff = (uint32_t)(lane & 15) * FPIT;

    for (int jt = 0; jt < 16; jt++) {
        __syncthreads();
        int j0 = jt * 64;
#pragma unroll
        for (int it = 0; it < 8; it++) {
            int idx = tid + (it & 3) * 256;  // 0..1023
            int r = idx >> 4;                // 0..63
            int f4 = idx & 15;
            size_t go = (size_t)(j0 + r) * 3072 + f4 * 4;
            uint32_t so = (uint32_t)r * FPIT + (uint32_t)f4 * 8;
            if (it < 4) {
                *(uint2*)(smb + SKH + so) = *(const uint2*)(kbh + go);
                *(uint2*)(smb + SKL + so) = *(const uint2*)(kbl + go);
            } else {
                *(uint2*)(smb + SVH + so) = *(const uint2*)(vbh + go);
                *(uint2*)(smb + SVL + so) = *(const uint2*)(vbl + go);
            }
        }
        __syncthreads();

        // ---- S = Q K^T ----
        float S[8][4];
#pragma unroll
        for (int jj = 0; jj < 8; jj++)
#pragma unroll
            for (int q = 0; q < 4; q++) S[jj][q] = 0.f;

#pragma unroll
        for (int ks = 0; ks < 4; ks++) {
            uint32_t qhv[4], qlv[4];
            uint32_t qa = (uint32_t)(w * 16) * FPIT + ks * 32 + aoff;
            ldm4(qhv, sb + SQH + qa);
            ldm4(qlv, sb + SQL + qa);
#pragma unroll
            for (int jj = 0; jj < 8; jj++) {
                uint32_t kh[2], kl[2];
                uint32_t ka = (uint32_t)(jj * 8) * FPIT + ks * 32 + koff;
                ldm2(kh, sb + SKH + ka);
                ldm2(kl, sb + SKL + ka);
                mma16816(S[jj], qhv, kh);
                mma16816(S[jj], qhv, kl);
                mma16816(S[jj], qlv, kh);
            }
        }

        // ---- online softmax ----
        float mt0 = S[0][0], mt1 = S[0][2];
#pragma unroll
        for (int jj = 0; jj < 8; jj++) {
            mt0 = fmaxf(mt0, fmaxf(S[jj][0], S[jj][1]));
            mt1 = fmaxf(mt1, fmaxf(S[jj][2], S[jj][3]));
        }
        mt0 = fmaxf(mt0, __shfl_xor_sync(0xffffffffu, mt0, 1));
        mt0 = fmaxf(mt0, __shfl_xor_sync(0xffffffffu, mt0, 2));
        mt1 = fmaxf(mt1, __shfl_xor_sync(0xffffffffu, mt1, 1));
        mt1 = fmaxf(mt1, __shfl_xor_sync(0xffffffffu, mt1, 2));
        float mn0 = fmaxf(m0, mt0), mn1 = fmaxf(m1, mt1);
        float sc0 = __expf(m0 - mn0), sc1 = __expf(m1 - mn1);

        uint32_t Ph[8][2], Pl[8][2];
        float ls0 = 0.f, ls1 = 0.f;
#pragma unroll
        for (int jj = 0; jj < 8; jj++) {
            float p0 = __expf(S[jj][0] - mn0);
            float p1 = __expf(S[jj][1] - mn0);
            float p2 = __expf(S[jj][2] - mn1);
            float p3 = __expf(S[jj][3] - mn1);
            ls0 += p0 + p1;
            ls1 += p2 + p3;
            split2(p0, p1, Ph[jj][0], Pl[jj][0]);
            split2(p2, p3, Ph[jj][1], Pl[jj][1]);
        }
        ls0 += __shfl_xor_sync(0xffffffffu, ls0, 1);
        ls0 += __shfl_xor_sync(0xffffffffu, ls0, 2);
        ls1 += __shfl_xor_sync(0xffffffffu, ls1, 1);
        ls1 += __shfl_xor_sync(0xffffffffu, ls1, 2);
        l0 = l0 * sc0 + ls0;
        l1 = l1 * sc1 + ls1;
        m0 = mn0;
        m1 = mn1;

#pragma unroll
        for (int nd = 0; nd < 8; nd++) {
            O[nd][0] *= sc0; O[nd][1] *= sc0;
            O[nd][2] *= sc1; O[nd][3] *= sc1;
        }

        // ---- O += P V ----
#pragma unroll
        for (int kk = 0; kk < 4; kk++) {
            uint32_t ah[4] = {Ph[2 * kk][0], Ph[2 * kk][1], Ph[2 * kk + 1][0], Ph[2 * kk + 1][1]};
            uint32_t al[4] = {Pl[2 * kk][0], Pl[2 * kk][1], Pl[2 * kk + 1][0], Pl[2 * kk + 1][1]};
#pragma unroll
            for (int nd = 0; nd < 8; nd++) {
                uint32_t vh[2], vl[2];
                uint32_t va = (uint32_t)(kk * 16) * FPIT + nd * 16 + voff;
                ldm2t(vh, sb + SVH + va);
                ldm2t(vl, sb + SVL + va);
                mma16816(O[nd], ah, vh);
                mma16816(O[nd], ah, vl);
                mma16816(O[nd], al, vh);
            }
        }
    }

    // ---- epilogue: divide by l, write split to aoh/aol ----
    float inv0 = 1.0f / l0, inv1 = 1.0f / l1;
    int r0 = b * 1024 + i0 + w * 16 + (lane >> 2);
    int cg = h * DH + (lane & 3) * 2;
#pragma unroll
    for (int nd = 0; nd < 8; nd++) {
        uint32_t hi, lo;
        split2(O[nd][0] * inv0, O[nd][1] * inv0, hi, lo);
        *(uint32_t*)(aoh + (size_t)r0 * 1024 + cg + nd * 8) = hi;
        *(uint32_t*)(aol + (size_t)r0 * 1024 + cg + nd * 8) = lo;
        split2(O[nd][2] * inv1, O[nd][3] * inv1, hi, lo);
        *(uint32_t*)(aoh + (size_t)(r0 + 8) * 1024 + cg + nd * 8) = hi;
        *(uint32_t*)(aol + (size_t)(r0 + 8) * 1024 + cg + nd * 8) = lo;
    }
}

// ---------------- launch ----------------
extern "C" void kernel_launch(void* const* d_in, const int* in_sizes, int n_in,
                              void* d_out, int out_size) {
    const float* x     = (const float*)d_in[0];
    const float* ln_g  = (const float*)d_in[1];
    const float* qg    = (const float*)d_in[2];
    const float* kg    = (const float*)d_in[3];
    const float* wqkv  = (const float*)d_in[4];
    const float* wout  = (const float*)d_in[5];
    float* out = (float*)d_out;

    float* qkv;
    __nv_bfloat16 *xnh, *xnl, *qh, *ql, *aoh, *aol, *wth, *wtl, *w2h, *w2l;
    cudaGetSymbolAddress((void**)&qkv, g_qkv);
    cudaGetSymbolAddress((void**)&xnh, g_xnh);
    cudaGetSymbolAddress((void**)&xnl, g_xnl);
    cudaGetSymbolAddress((void**)&qh, g_qh);
    cudaGetSymbolAddress((void**)&ql, g_ql);
    cudaGetSymbolAddress((void**)&aoh, g_aoh);
    cudaGetSymbolAddress((void**)&aol, g_aol);
    cudaGetSymbolAddress((void**)&wth, g_wth);
    cudaGetSymbolAddress((void**)&wtl, g_wtl);
    cudaGetSymbolAddress((void**)&w2h, g_w2h);
    cudaGetSymbolAddress((void**)&w2l, g_w2l);

    cudaFuncSetAttribute((const void*)attn_mma,
                         cudaFuncAttributeMaxDynamicSharedMemorySize, ATTN_SMEM);
    cudaFuncSetAttribute((const void*)gemm_split,
                         cudaFuncAttributeMaxDynamicSharedMemorySize, GEMM_SMEM);

    ln_kernel<<<8192, 256>>>(x, ln_g, xnh, xnl);
    transpose_split<<<dim3(3072 / 32, 1024 / 32), 256>>>(wqkv, wth, wtl, 1024, 3072);
    transpose_split<<<dim3(1024 / 32, 1024 / 32), 256>>>(wout, w2h, w2l, 1024, 1024);
    gemm_split<<<dim3(3072 / 128, 8192 / 128), 256, GEMM_SMEM>>>(xnh, xnl, wth, wtl, qkv,
                                                                 8192, 3072, 1024);
    rms_split<<<49152, 256>>>(qkv, qg, kg, qh, ql);
    attn_mma<<<dim3(8, 128), 256, ATTN_SMEM>>>(qh, ql, aoh, aol);
    gemm_split<<<dim3(1024 / 128, 8192 / 128), 256, GEMM_SMEM>>>(aoh, aol, w2h, w2l, out,
                                                                 8192, 1024, 1024);
}